// round 1
// baseline (speedup 1.0000x reference)
#include <cuda_runtime.h>
#include <cstdint>

#define BB 4
#define SS 2048
#define DD 768
#define NH 4
#define DH 192
#define KW 4
#define G4 4
#define EPSV 1e-5f

// Scratch (device globals -- no allocation allowed)
__device__ float g_xconv[BB*SS*DD];               // 25 MB
__device__ float g_gates[BB*NH*SS*G4*DH];         // 100 MB  [b][h][s][g][e]
__device__ float g_y[BB*NH*SS*DH];                // 25 MB   [b][h][s][e]

// ---------------------------------------------------------------------------
// Kernel 1: causal depthwise conv (K=4) + swish
// ---------------------------------------------------------------------------
__global__ void conv_swish_kernel(const float* __restrict__ x,
                                  const float* __restrict__ ck,
                                  const float* __restrict__ cb) {
    int idx = blockIdx.x * blockDim.x + threadIdx.x;     // per float4
    const int D4 = DD / 4;
    if (idx >= BB * SS * D4) return;
    int c4 = idx % D4;
    int s  = (idx / D4) % SS;
    int b  = idx / (SS * D4);

    float4 acc = *(const float4*)&cb[c4 * 4];
    const float4* x4 = (const float4*)x;
#pragma unroll
    for (int j = 0; j < KW; j++) {
        int sj = s - (KW - 1) + j;
        if (sj >= 0) {
            float4 xv = x4[(b * SS + sj) * D4 + c4];
            float4 kv = *(const float4*)&ck[j * DD + c4 * 4];
            acc.x = fmaf(xv.x, kv.x, acc.x);
            acc.y = fmaf(xv.y, kv.y, acc.y);
            acc.z = fmaf(xv.z, kv.z, acc.z);
            acc.w = fmaf(xv.w, kv.w, acc.w);
        }
    }
    acc.x = acc.x / (1.f + __expf(-acc.x));
    acc.y = acc.y / (1.f + __expf(-acc.y));
    acc.z = acc.z / (1.f + __expf(-acc.z));
    acc.w = acc.w / (1.f + __expf(-acc.w));
    ((float4*)g_xconv)[idx] = acc;
}

// ---------------------------------------------------------------------------
// Kernel 2: gate pre-activation GEMMs
//   For (h,g): C[8192 x 192] = A[8192 x 192] * W[192 x 192]  (+ cell_bias)
//   A = x_conv for gates i,f ; A = x for gates z,o
//   Output layout g_gates[b][h][s][g][e]
// ---------------------------------------------------------------------------
__global__ __launch_bounds__(256)
void gate_gemm_kernel(const float* __restrict__ x,
                      const float* __restrict__ Wi, const float* __restrict__ Wf,
                      const float* __restrict__ Wz, const float* __restrict__ Wo,
                      const float* __restrict__ cbias) {
    int hg = blockIdx.y;
    int h = hg >> 2;
    int g = hg & 3;
    const float* A = (g < 2) ? g_xconv : x;
    const float* W = (g == 0) ? Wi : (g == 1) ? Wf : (g == 2) ? Wz : Wo;
    W += h * DH * DH;
    int row0 = blockIdx.x * 128;

    __shared__ float As[16][128];
    __shared__ float Ws[16][DH];

    int tid = threadIdx.x;
    int tr = tid >> 4;           // 0..15 (row group)
    int tc = tid & 15;           // 0..15 (col group)

    float acc[8][12];
#pragma unroll
    for (int i = 0; i < 8; i++)
#pragma unroll
        for (int j = 0; j < 12; j++) acc[i][j] = 0.f;

    for (int k0 = 0; k0 < DH; k0 += 16) {
        // A tile: 128 rows x 16 k
#pragma unroll
        for (int i = 0; i < 2; i++) {
            int lidx = tid + i * 256;         // 0..511 float4 slots
            int r  = lidx >> 2;               // 0..127
            int kk = (lidx & 3) * 4;
            int grow = row0 + r;
            float4 v = *(const float4*)&A[grow * DD + h * DH + k0 + kk];
            As[kk + 0][r] = v.x; As[kk + 1][r] = v.y;
            As[kk + 2][r] = v.z; As[kk + 3][r] = v.w;
        }
        // W tile: 16 x 192
#pragma unroll
        for (int i = 0; i < 3; i++) {
            int lidx = tid + i * 256;         // 0..767
            int kr = lidx / 48;
            int c4 = lidx % 48;
            float4 v = *(const float4*)&W[(k0 + kr) * DH + c4 * 4];
            *(float4*)&Ws[kr][c4 * 4] = v;
        }
        __syncthreads();
#pragma unroll
        for (int kk = 0; kk < 16; kk++) {
            float a[8], bb[12];
#pragma unroll
            for (int i = 0; i < 8; i += 4) {
                float4 v = *(const float4*)&As[kk][tr * 8 + i];
                a[i] = v.x; a[i + 1] = v.y; a[i + 2] = v.z; a[i + 3] = v.w;
            }
#pragma unroll
            for (int j = 0; j < 12; j += 4) {
                float4 v = *(const float4*)&Ws[kk][tc * 12 + j];
                bb[j] = v.x; bb[j + 1] = v.y; bb[j + 2] = v.z; bb[j + 3] = v.w;
            }
#pragma unroll
            for (int i = 0; i < 8; i++)
#pragma unroll
                for (int j = 0; j < 12; j++)
                    acc[i][j] = fmaf(a[i], bb[j], acc[i][j]);
        }
        __syncthreads();
    }

    // epilogue: fold cell_bias, write [b][h][s][g][e]
#pragma unroll
    for (int i = 0; i < 8; i++) {
        int grow = row0 + tr * 8 + i;
        int b = grow >> 11;                 // /2048
        int s = grow & 2047;
        long base = (long)((b * NH + h) * SS + s) * (G4 * DH) + g * DH + tc * 12;
#pragma unroll
        for (int j = 0; j < 12; j++)
            g_gates[base + j] = acc[i][j] + cbias[g * DD + h * DH + tc * 12 + j];
    }
}

// ---------------------------------------------------------------------------
// Kernel 3: sequential sLSTM scan.
//   64 CTAs, clusters of 4 (one cluster per (b,h) chain, one CTA per gate).
//   Each CTA holds its 192x192 gate recurrence matrix in REGISTERS
//   (96 weights/thread @ 384 threads). Per step:
//     matvec -> reduce -> +gate preact -> DSMEM multicast of pre ->
//     cluster barrier -> replicated gating -> h/c/n/m update in smem.
// ---------------------------------------------------------------------------
__device__ __forceinline__ uint32_t smem_u32(const void* p) {
    uint32_t a;
    asm("{ .reg .u64 t; cvta.to.shared.u64 t, %1; cvt.u32.u64 %0, t; }"
        : "=r"(a) : "l"(p));
    return a;
}

__global__ void __cluster_dims__(4, 1, 1) __launch_bounds__(384, 1)
scan_kernel(const float* __restrict__ R) {
    int g = blockIdx.x & 3;        // cluster rank == gate
    int chain = blockIdx.x >> 2;   // b*NH + h
    int h = chain & 3;

    __shared__ float h_sm[DH], c_sm[DH], n_sm[DH], m_sm[DH];
    __shared__ float red[384];
    __shared__ float pre[2][G4][DH];

    int t = threadIdx.x;
    int e = t % DH;
    int p = t / DH;                // 0 or 1 (d-partition)
    int d0 = p * 96;

    // Load this CTA's gate matrix R[g][h][:][:] into registers:
    // thread (e,p) holds R[g][h][d0+j][e], j=0..95
    float w[96];
    {
        const float* Rb = R + (long)((g * NH + h) * DH) * DH + e;
#pragma unroll
        for (int j = 0; j < 96; j++) w[j] = Rb[(d0 + j) * DH];
    }

    if (t < DH) { h_sm[t] = 0.f; c_sm[t] = 0.f; n_sm[t] = 0.f; m_sm[t] = 0.f; }
    __syncthreads();

    const float* Gp = g_gates + (long)(chain * SS) * (G4 * DH) + g * DH + e;
    float gcur = (t < DH) ? Gp[0] : 0.f;

    float* Yp = g_y + (long)chain * SS * DH;

    for (int step = 0; step < SS; step++) {
        int buf = step & 1;

        // --- matvec: acc = sum_d h[d] * w ---
        float a0 = 0.f, a1 = 0.f, a2 = 0.f, a3 = 0.f;
        const float4* h4 = (const float4*)(h_sm + d0);   // uniform per warp -> broadcast LDS
#pragma unroll
        for (int jj = 0; jj < 24; jj++) {
            float4 hv = h4[jj];
            a0 = fmaf(w[4 * jj + 0], hv.x, a0);
            a1 = fmaf(w[4 * jj + 1], hv.y, a1);
            a2 = fmaf(w[4 * jj + 2], hv.z, a2);
            a3 = fmaf(w[4 * jj + 3], hv.w, a3);
        }
        red[t] = (a0 + a1) + (a2 + a3);
        __syncthreads();

        if (t < DH) {
            float preval = red[t] + red[t + DH] + gcur;
            // multicast pre[g][e] to all 4 CTAs in the cluster (incl. self)
            uint32_t laddr = smem_u32(&pre[buf][g][t]);
#pragma unroll
            for (int r = 0; r < 4; r++) {
                uint32_t raddr;
                asm volatile("mapa.shared::cluster.u32 %0, %1, %2;"
                             : "=r"(raddr) : "r"(laddr), "r"(r));
                asm volatile("st.shared::cluster.f32 [%0], %1;"
                             :: "r"(raddr), "f"(preval) : "memory");
            }
            // prefetch next step's gate pre-activation
            if (step + 1 < SS) gcur = Gp[(long)(step + 1) * (G4 * DH)];
        }

        asm volatile("barrier.cluster.arrive.aligned;" ::: "memory");
        asm volatile("barrier.cluster.wait.aligned;" ::: "memory");

        // --- gating (replicated in every CTA) ---
        if (t < DH) {
            float iv = pre[buf][0][t];
            float fv = pre[buf][1][t];
            float zv = pre[buf][2][t];
            float ov = pre[buf][3][t];
            float mo = m_sm[t];
            float mn = fmaxf(fv + mo, iv);
            float ia = __expf(iv - mn);
            float fa = __expf(fv + mo - mn);
            float cn = fmaf(ia, tanhf(zv), fa * c_sm[t]);
            float nn = fa * n_sm[t] + ia;
            float hn = (cn / nn) * (1.f / (1.f + __expf(-ov)));
            h_sm[t] = hn; c_sm[t] = cn; n_sm[t] = nn; m_sm[t] = mn;
            if (g == 0) Yp[(long)step * DH + t] = hn;
        }
        __syncthreads();
    }
}

// ---------------------------------------------------------------------------
// Kernel 4: per-head layernorm + scale, reorder to (B,S,D)
//   one warp per (b,h,s) row of 192
// ---------------------------------------------------------------------------
__global__ void ln_kernel(const float* __restrict__ gn, float* __restrict__ out) {
    int gtid = blockIdx.x * blockDim.x + threadIdx.x;
    int warp = gtid >> 5;
    int lane = gtid & 31;
    if (warp >= BB * NH * SS) return;

    int s = warp % SS;
    int chain = warp / SS;
    int b = chain >> 2;
    int h = chain & 3;

    const float* y = g_y + (long)warp * DH;
    float v[6];
    float sum = 0.f, sq = 0.f;
#pragma unroll
    for (int k = 0; k < 6; k++) {
        v[k] = y[lane + 32 * k];
        sum += v[k];
        sq  = fmaf(v[k], v[k], sq);
    }
#pragma unroll
    for (int o = 16; o > 0; o >>= 1) {
        sum += __shfl_xor_sync(0xffffffffu, sum, o);
        sq  += __shfl_xor_sync(0xffffffffu, sq, o);
    }
    float mu  = sum * (1.f / DH);
    float var = sq * (1.f / DH) - mu * mu;
    float inv = rsqrtf(var + EPSV);

    long obase = (long)(b * SS + s) * DD + h * DH;
#pragma unroll
    for (int k = 0; k < 6; k++) {
        int ei = lane + 32 * k;
        out[obase + ei] = (v[k] - mu) * inv * gn[h * DH + ei];
    }
}

// ---------------------------------------------------------------------------
extern "C" void kernel_launch(void* const* d_in, const int* in_sizes, int n_in,
                              void* d_out, int out_size) {
    const float* x     = (const float*)d_in[0];
    const float* ck    = (const float*)d_in[1];
    const float* cb    = (const float*)d_in[2];
    const float* Wi    = (const float*)d_in[3];
    const float* Wf    = (const float*)d_in[4];
    const float* Wz    = (const float*)d_in[5];
    const float* Wo    = (const float*)d_in[6];
    const float* R     = (const float*)d_in[7];
    const float* cbias = (const float*)d_in[8];
    const float* gn    = (const float*)d_in[9];
    float* out = (float*)d_out;

    // 1) conv + swish
    {
        int total = BB * SS * (DD / 4);
        conv_swish_kernel<<<(total + 255) / 256, 256>>>(x, ck, cb);
    }
    // 2) gate GEMMs
    {
        dim3 grid(BB * SS / 128, NH * G4);
        gate_gemm_kernel<<<grid, 256>>>(x, Wi, Wf, Wz, Wo, cbias);
    }
    // 3) sequential scan (16 chains x 4 gate-CTAs, cluster=4)
    scan_kernel<<<BB * NH * G4, 384>>>(R);
    // 4) layernorm
    {
        int warps = BB * NH * SS;
        int threads = warps * 32;
        ln_kernel<<<(threads + 255) / 256, 256>>>(gn, out);
    }
    (void)in_sizes; (void)n_in; (void)out_size;
}

// round 2
// speedup vs baseline: 1.5360x; 1.5360x over previous
#include <cuda_runtime.h>
#include <cstdint>

#define BB 4
#define SS 2048
#define DD 768
#define NH 4
#define DH 192
#define KW 4
#define G4 4
#define EPSV 1e-5f

typedef unsigned long long u64t;

// Scratch (device globals -- no allocation allowed)
__device__ float g_xconv[BB*SS*DD];               // 25 MB
__device__ float g_gates[BB*NH*SS*G4*DH];         // 100 MB  [b][h][s][g][e]
__device__ float g_y[BB*NH*SS*DH];                // 25 MB   [b][h][s][e]

#define FMA2(d, a, b, c) \
    asm("fma.rn.f32x2 %0, %1, %2, %3;" : "=l"(d) : "l"(a), "l"(b), "l"(c))

__device__ __forceinline__ u64t pack2(float lo, float hi) {
    u64t r = ((u64t)__float_as_uint(hi) << 32) | (u64t)__float_as_uint(lo);
    return r;
}

// ---------------------------------------------------------------------------
// Kernel 1: causal depthwise conv (K=4) + swish
// ---------------------------------------------------------------------------
__global__ void conv_swish_kernel(const float* __restrict__ x,
                                  const float* __restrict__ ck,
                                  const float* __restrict__ cb) {
    int idx = blockIdx.x * blockDim.x + threadIdx.x;     // per float4
    const int D4 = DD / 4;
    if (idx >= BB * SS * D4) return;
    int c4 = idx % D4;
    int s  = (idx / D4) % SS;
    int b  = idx / (SS * D4);

    float4 acc = *(const float4*)&cb[c4 * 4];
    const float4* x4 = (const float4*)x;
#pragma unroll
    for (int j = 0; j < KW; j++) {
        int sj = s - (KW - 1) + j;
        if (sj >= 0) {
            float4 xv = x4[(b * SS + sj) * D4 + c4];
            float4 kv = *(const float4*)&ck[j * DD + c4 * 4];
            acc.x = fmaf(xv.x, kv.x, acc.x);
            acc.y = fmaf(xv.y, kv.y, acc.y);
            acc.z = fmaf(xv.z, kv.z, acc.z);
            acc.w = fmaf(xv.w, kv.w, acc.w);
        }
    }
    acc.x = acc.x / (1.f + __expf(-acc.x));
    acc.y = acc.y / (1.f + __expf(-acc.y));
    acc.z = acc.z / (1.f + __expf(-acc.z));
    acc.w = acc.w / (1.f + __expf(-acc.w));
    ((float4*)g_xconv)[idx] = acc;
}

// ---------------------------------------------------------------------------
// Kernel 2: gate pre-activation GEMMs (packed f32x2 FMAs)
//   For (h,g): C[8192 x 192] = A[8192 x 192] * W[192 x 192]  (+ cell_bias)
// ---------------------------------------------------------------------------
__global__ __launch_bounds__(256)
void gate_gemm_kernel(const float* __restrict__ x,
                      const float* __restrict__ Wi, const float* __restrict__ Wf,
                      const float* __restrict__ Wz, const float* __restrict__ Wo,
                      const float* __restrict__ cbias) {
    int hg = blockIdx.y;
    int h = hg >> 2;
    int g = hg & 3;
    const float* A = (g < 2) ? g_xconv : x;
    const float* W = (g == 0) ? Wi : (g == 1) ? Wf : (g == 2) ? Wz : Wo;
    W += h * DH * DH;
    int row0 = blockIdx.x * 128;

    __shared__ __align__(16) float As[16][128];
    __shared__ __align__(16) float Ws[16][DH];

    int tid = threadIdx.x;
    int tr = tid >> 4;           // 0..15 (row group)
    int tc = tid & 15;           // 0..15 (col group)

    u64t acc2[8][6];             // 8 rows x 6 col-pairs (12 cols)
#pragma unroll
    for (int i = 0; i < 8; i++)
#pragma unroll
        for (int j = 0; j < 6; j++) acc2[i][j] = 0ull;

    for (int k0 = 0; k0 < DH; k0 += 16) {
        // A tile: 128 rows x 16 k
#pragma unroll
        for (int i = 0; i < 2; i++) {
            int lidx = tid + i * 256;         // 0..511 float4 slots
            int r  = lidx >> 2;               // 0..127
            int kk = (lidx & 3) * 4;
            int grow = row0 + r;
            float4 v = *(const float4*)&A[grow * DD + h * DH + k0 + kk];
            As[kk + 0][r] = v.x; As[kk + 1][r] = v.y;
            As[kk + 2][r] = v.z; As[kk + 3][r] = v.w;
        }
        // W tile: 16 x 192
#pragma unroll
        for (int i = 0; i < 3; i++) {
            int lidx = tid + i * 256;         // 0..767
            int kr = lidx / 48;
            int c4 = lidx % 48;
            float4 v = *(const float4*)&W[(k0 + kr) * DH + c4 * 4];
            *(float4*)&Ws[kr][c4 * 4] = v;
        }
        __syncthreads();
#pragma unroll
        for (int kk = 0; kk < 16; kk++) {
            float a[8];
#pragma unroll
            for (int i = 0; i < 8; i += 4) {
                float4 v = *(const float4*)&As[kk][tr * 8 + i];
                a[i] = v.x; a[i + 1] = v.y; a[i + 2] = v.z; a[i + 3] = v.w;
            }
            u64t bp[6];
            const ulonglong2* wrow = (const ulonglong2*)&Ws[kk][tc * 12];
#pragma unroll
            for (int m = 0; m < 3; m++) {
                ulonglong2 v = wrow[m];
                bp[2 * m] = v.x; bp[2 * m + 1] = v.y;
            }
#pragma unroll
            for (int i = 0; i < 8; i++) {
                u64t ai = pack2(a[i], a[i]);
#pragma unroll
                for (int m = 0; m < 6; m++)
                    FMA2(acc2[i][m], ai, bp[m], acc2[i][m]);
            }
        }
        __syncthreads();
    }

    // epilogue: fold cell_bias, write [b][h][s][g][e]
#pragma unroll
    for (int i = 0; i < 8; i++) {
        int grow = row0 + tr * 8 + i;
        int b = grow >> 11;                 // /2048
        int s = grow & 2047;
        long base = (long)((b * NH + h) * SS + s) * (G4 * DH) + g * DH + tc * 12;
#pragma unroll
        for (int m = 0; m < 6; m++) {
            float lo = __uint_as_float((unsigned)(acc2[i][m] & 0xffffffffull));
            float hi = __uint_as_float((unsigned)(acc2[i][m] >> 32));
            g_gates[base + 2 * m]     = lo + cbias[g * DD + h * DH + tc * 12 + 2 * m];
            g_gates[base + 2 * m + 1] = hi + cbias[g * DD + h * DH + tc * 12 + 2 * m + 1];
        }
    }
}

// ---------------------------------------------------------------------------
// Kernel 3: sequential sLSTM scan.
//   64 CTAs, clusters of 4 (one cluster per (b,h) chain, one CTA per gate).
//   Gate matrix (192x192) register-resident as f32x2 pairs. Per step:
//   packed matvec -> st.async multicast of pre (+mbarrier tx) ->
//   mbarrier parity wait -> replicated gating -> next step.
// ---------------------------------------------------------------------------
__device__ __forceinline__ uint32_t smem_u32(const void* p) {
    uint32_t a;
    asm("{ .reg .u64 t; cvta.to.shared.u64 t, %1; cvt.u32.u64 %0, t; }"
        : "=r"(a) : "l"(p));
    return a;
}

__global__ void __cluster_dims__(4, 1, 1) __launch_bounds__(384, 1)
scan_kernel(const float* __restrict__ R) {
    int g = blockIdx.x & 3;        // cluster rank == gate
    int chain = blockIdx.x >> 2;   // b*NH + h
    int h = chain & 3;

    __shared__ __align__(16) float h_sm[DH];
    __shared__ float c_sm[DH], n_sm[DH], m_sm[DH];
    __shared__ float red[384];
    __shared__ __align__(16) float pre[2][G4][DH];
    __shared__ __align__(8) u64t mbar[2];

    int t = threadIdx.x;
    int e = t % DH;
    int p = t / DH;                // 0 or 1 (d-partition)
    int d0 = p * 96;

    // Load this CTA's gate matrix R[g][h][:][:] into registers as pairs:
    // thread (e,p) holds pairs (R[d0+2j][e], R[d0+2j+1][e]), j=0..47
    u64t w2[48];
    {
        const float* Rb = R + (long)((g * NH + h) * DH) * DH + e;
#pragma unroll
        for (int j = 0; j < 48; j++)
            w2[j] = pack2(Rb[(d0 + 2 * j) * DH], Rb[(d0 + 2 * j + 1) * DH]);
    }

    if (t < DH) { h_sm[t] = 0.f; c_sm[t] = 0.f; n_sm[t] = 0.f; m_sm[t] = 0.f; }
    if (t == 0) {
        asm volatile("mbarrier.init.shared.b64 [%0], 1;" :: "r"(smem_u32(&mbar[0])) : "memory");
        asm volatile("mbarrier.init.shared.b64 [%0], 1;" :: "r"(smem_u32(&mbar[1])) : "memory");
    }
    __syncthreads();
    // cluster-wide: all mbarriers initialized before any st.async
    asm volatile("barrier.cluster.arrive.aligned;" ::: "memory");
    asm volatile("barrier.cluster.wait.aligned;" ::: "memory");

    // Pre-arm both phase buffers: 4 CTAs x 192 elems x 4 bytes = 3072 bytes
    if (t == 0) {
        asm volatile("mbarrier.arrive.expect_tx.shared.b64 _, [%0], %1;"
                     :: "r"(smem_u32(&mbar[0])), "r"(3072u) : "memory");
        asm volatile("mbarrier.arrive.expect_tx.shared.b64 _, [%0], %1;"
                     :: "r"(smem_u32(&mbar[1])), "r"(3072u) : "memory");
    }

    // Hoist mapa'd remote addresses (loop-invariant)
    uint32_t ra[4], rb[4];
    {
        uint32_t lpre = smem_u32(&pre[0][g][e]);
        uint32_t lmb  = smem_u32(&mbar[0]);
#pragma unroll
        for (int r = 0; r < 4; r++) {
            asm("mapa.shared::cluster.u32 %0, %1, %2;" : "=r"(ra[r]) : "r"(lpre), "r"(r));
            asm("mapa.shared::cluster.u32 %0, %1, %2;" : "=r"(rb[r]) : "r"(lmb), "r"(r));
        }
    }

    const float* Gp = g_gates + (long)(chain * SS) * (G4 * DH) + g * DH + e;
    float gcur = (t < DH) ? Gp[0] : 0.f;

    float* Yp = g_y + (long)chain * SS * DH;

    for (int step = 0; step < SS; step++) {
        int buf = step & 1;
        int ph = (step >> 1) & 1;

        // --- packed matvec: partial = sum over d in [d0, d0+96) of h[d]*R[d][e]
        u64t acc0 = 0ull, acc1 = 0ull;
        const ulonglong2* h2v = (const ulonglong2*)(h_sm + d0);  // uniform -> bcast LDS
#pragma unroll
        for (int jj = 0; jj < 24; jj++) {
            ulonglong2 hv = h2v[jj];
            FMA2(acc0, w2[2 * jj],     hv.x, acc0);
            FMA2(acc1, w2[2 * jj + 1], hv.y, acc1);
        }
        float s0 = __uint_as_float((unsigned)(acc0 & 0xffffffffull));
        float s1 = __uint_as_float((unsigned)(acc0 >> 32));
        float s2 = __uint_as_float((unsigned)(acc1 & 0xffffffffull));
        float s3 = __uint_as_float((unsigned)(acc1 >> 32));
        float part = (s0 + s1) + (s2 + s3);
        red[t] = part;
        __syncthreads();

        if (t < DH) {
            float preval = part + red[t + DH] + gcur;
            uint32_t pofs = (uint32_t)buf * (G4 * DH * 4);
            uint32_t mofs = (uint32_t)buf * 8;
            // store + tx-signal to all 4 CTAs in one instruction each
#pragma unroll
            for (int r = 0; r < 4; r++) {
                asm volatile(
                    "st.async.shared::cluster.mbarrier::complete_tx::bytes.f32 [%0], %1, [%2];"
                    :: "r"(ra[r] + pofs), "f"(preval), "r"(rb[r] + mofs) : "memory");
            }
            // prefetch next step's gate pre-activation (off critical path)
            if (step + 1 < SS) gcur = Gp[(long)(step + 1) * (G4 * DH)];

            // wait for all 16 gate-slices of pre to arrive
            {
                uint32_t mb = smem_u32(&mbar[0]) + mofs;
                asm volatile(
                    "{\n\t"
                    ".reg .pred P1;\n\t"
                    "WAIT_%=:\n\t"
                    "mbarrier.try_wait.parity.acquire.cta.shared::cta.b64 P1, [%0], %1, 0x989680;\n\t"
                    "@P1 bra.uni DONE_%=;\n\t"
                    "bra.uni WAIT_%=;\n\t"
                    "DONE_%=:\n\t"
                    "}"
                    :: "r"(mb), "r"(ph) : "memory");
                if (t == 0) {
                    // re-arm this buffer for step+2 (we are now in its next phase)
                    asm volatile("mbarrier.arrive.expect_tx.shared.b64 _, [%0], %1;"
                                 :: "r"(mb), "r"(3072u) : "memory");
                }
            }

            // --- gating (replicated in every CTA) ---
            float iv = pre[buf][0][t];
            float fv = pre[buf][1][t];
            float zv = pre[buf][2][t];
            float ov = pre[buf][3][t];
            float mo = m_sm[t];
            float mn = fmaxf(fv + mo, iv);
            float ia = __expf(iv - mn);
            float fa = __expf(fv + mo - mn);
            float cn = fmaf(ia, tanhf(zv), fa * c_sm[t]);
            float nn = fmaf(fa, n_sm[t], ia);
            float hn = (cn / nn) * (1.f / (1.f + __expf(-ov)));
            h_sm[t] = hn; c_sm[t] = cn; n_sm[t] = nn; m_sm[t] = mn;
            if (g == 0) Yp[(long)step * DH + t] = hn;
        }
        __syncthreads();
    }
}

// ---------------------------------------------------------------------------
// Kernel 4: per-head layernorm + scale, reorder to (B,S,D)
//   one warp per (b,h,s) row of 192
// ---------------------------------------------------------------------------
__global__ void ln_kernel(const float* __restrict__ gn, float* __restrict__ out) {
    int gtid = blockIdx.x * blockDim.x + threadIdx.x;
    int warp = gtid >> 5;
    int lane = gtid & 31;
    if (warp >= BB * NH * SS) return;

    int s = warp % SS;
    int chain = warp / SS;
    int b = chain >> 2;
    int h = chain & 3;

    const float* y = g_y + (long)warp * DH;
    float v[6];
    float sum = 0.f, sq = 0.f;
#pragma unroll
    for (int k = 0; k < 6; k++) {
        v[k] = y[lane + 32 * k];
        sum += v[k];
        sq  = fmaf(v[k], v[k], sq);
    }
#pragma unroll
    for (int o = 16; o > 0; o >>= 1) {
        sum += __shfl_xor_sync(0xffffffffu, sum, o);
        sq  += __shfl_xor_sync(0xffffffffu, sq, o);
    }
    float mu  = sum * (1.f / DH);
    float var = sq * (1.f / DH) - mu * mu;
    float inv = rsqrtf(var + EPSV);

    long obase = (long)(b * SS + s) * DD + h * DH;
#pragma unroll
    for (int k = 0; k < 6; k++) {
        int ei = lane + 32 * k;
        out[obase + ei] = (v[k] - mu) * inv * gn[h * DH + ei];
    }
}

// ---------------------------------------------------------------------------
extern "C" void kernel_launch(void* const* d_in, const int* in_sizes, int n_in,
                              void* d_out, int out_size) {
    const float* x     = (const float*)d_in[0];
    const float* ck    = (const float*)d_in[1];
    const float* cb    = (const float*)d_in[2];
    const float* Wi    = (const float*)d_in[3];
    const float* Wf    = (const float*)d_in[4];
    const float* Wz    = (const float*)d_in[5];
    const float* Wo    = (const float*)d_in[6];
    const float* R     = (const float*)d_in[7];
    const float* cbias = (const float*)d_in[8];
    const float* gn    = (const float*)d_in[9];
    float* out = (float*)d_out;

    // 1) conv + swish
    {
        int total = BB * SS * (DD / 4);
        conv_swish_kernel<<<(total + 255) / 256, 256>>>(x, ck, cb);
    }
    // 2) gate GEMMs
    {
        dim3 grid(BB * SS / 128, NH * G4);
        gate_gemm_kernel<<<grid, 256>>>(x, Wi, Wf, Wz, Wo, cbias);
    }
    // 3) sequential scan (16 chains x 4 gate-CTAs, cluster=4)
    scan_kernel<<<BB * NH * G4, 384>>>(R);
    // 4) layernorm
    {
        int warps = BB * NH * SS;
        int threads = warps * 32;
        ln_kernel<<<(threads + 255) / 256, 256>>>(gn, out);
    }
    (void)in_sizes; (void)n_in; (void)out_size;
}